// round 1
// baseline (speedup 1.0000x reference)
#include <cuda_runtime.h>
#include <cuda_bf16.h>
#include <math.h>

// Problem dims
#define BB 16
#define TT 256
#define SS 256
#define NA 300
#define DD 512
#define HH 8
#define DKK 64
#define DFF 2048
#define LL 6

#define BT (BB*TT)            // 4096
#define BHTT ((long)BB*HH*TT*TT)  // 8388608 per layer-stack slice

// d_out layout (floats): x | self_attns | enc_attns | ast_attns
#define X_OFF    0L
#define SELF_OFF 2097152L
#define ENC_OFF  (SELF_OFF + (long)LL*BHTT)   // 52428800
#define AST_OFF  (ENC_OFF  + (long)LL*BHTT)   // 102760448

// ------------- scratch (static device arrays; no allocation) -------------
__device__ float g_x[BT*DD];
__device__ float g_t[BT*DD];
__device__ float g_q[BT*DD];
__device__ float g_k[BT*DD];
__device__ float g_v[BT*DD];
__device__ float g_c[BT*DD];
__device__ float g_h[BT*DFF];
__device__ float g_multi[BB*SS*DD];
__device__ float g_ast1[BB*SS*DD];
__device__ float g_aste[BB*SS*DD];
__device__ float g_mm[BB*SS*SS];
__device__ float g_mmctx[BB*SS*DD];

// ---------------------------------------------------------------------
// sgemm: C[M,N] = A[M,K] @ B[K,N]  (row-major, M%128==0, N%128==0, K%8==0)
// optional accumulate into C, optional relu epilogue.
// 128x128 tile, BK=8, 256 threads, 8x8 micro-tile.
// ---------------------------------------------------------------------
template<bool RELU, bool ACC>
__global__ __launch_bounds__(256) void sgemm_k(
    const float* __restrict__ A, const float* __restrict__ B,
    float* __restrict__ C, int M, int N, int K)
{
    __shared__ float As[8][128];
    __shared__ float Bs[8][128];
    const int tid = threadIdx.x;
    const int trow = tid / 16;      // 0..15
    const int tcol = tid % 16;      // 0..15
    const int bx = blockIdx.x, by = blockIdx.y;

    const float* Ab = A + (long)by * 128 * K;
    const float* Bb = B + (long)bx * 128;

    const int aRow = tid >> 1;            // 0..127
    const int aCol = (tid & 1) * 4;       // 0 or 4
    const int bRow = tid >> 5;            // 0..7
    const int bCol = (tid & 31) * 4;      // 0..124

    float acc[8][8];
    #pragma unroll
    for (int i = 0; i < 8; i++)
        #pragma unroll
        for (int j = 0; j < 8; j++) acc[i][j] = 0.f;

    for (int k0 = 0; k0 < K; k0 += 8) {
        float4 av = *reinterpret_cast<const float4*>(Ab + (long)aRow * K + k0 + aCol);
        As[aCol+0][aRow] = av.x; As[aCol+1][aRow] = av.y;
        As[aCol+2][aRow] = av.z; As[aCol+3][aRow] = av.w;
        float4 bv = *reinterpret_cast<const float4*>(Bb + (long)(k0 + bRow) * N + bCol);
        *reinterpret_cast<float4*>(&Bs[bRow][bCol]) = bv;
        __syncthreads();
        #pragma unroll
        for (int kk = 0; kk < 8; kk++) {
            float a[8], b[8];
            #pragma unroll
            for (int i = 0; i < 8; i++) a[i] = As[kk][trow*8 + i];
            #pragma unroll
            for (int j = 0; j < 8; j++) b[j] = Bs[kk][tcol*8 + j];
            #pragma unroll
            for (int i = 0; i < 8; i++)
                #pragma unroll
                for (int j = 0; j < 8; j++)
                    acc[i][j] += a[i] * b[j];
        }
        __syncthreads();
    }

    float* Cb = C + ((long)by*128 + trow*8) * N + bx*128 + tcol*8;
    #pragma unroll
    for (int i = 0; i < 8; i++)
        #pragma unroll
        for (int j = 0; j < 8; j++) {
            float v = acc[i][j];
            if (ACC) v += Cb[(long)i*N + j];
            if (RELU) v = fmaxf(v, 0.f);
            Cb[(long)i*N + j] = v;
        }
}

// ---------------------------------------------------------------------
// batched C[z] = scale * A[z] @ B[z]^T, with optional masking (-1e9).
// A: MxK row-major (lda), B: NxK row-major (ldb).
// offsets: Aoff = (z/Hh)*strA + (z%Hh)*offHA  (same pattern for B),
// Coff = z*strC.  MASK: 0 none, 1 pad|causal (tok), 2 pad (tok).
// 64x64 tile, BK=16, 256 threads, 4x4 micro. K%16==0.
// ---------------------------------------------------------------------
template<int MASK>
__global__ __launch_bounds__(256) void bgemm_abT(
    const float* __restrict__ A, const float* __restrict__ B,
    float* __restrict__ C,
    int M, int N, int K, int lda, int ldb,
    long strA, long offHA, long strB, long offHB, long strC,
    int Hh, float scale, const int* __restrict__ tok, int tokStride)
{
    __shared__ float As[16][64];
    __shared__ float Bs[16][64];
    const int tid = threadIdx.x;
    const int trow = tid / 16, tcol = tid % 16;
    const int z = blockIdx.z;
    const int bb = z / Hh, hh = z % Hh;

    const float* Ab = A + (long)bb*strA + (long)hh*offHA + (long)blockIdx.y*64*lda;
    const float* Bb = B + (long)bb*strB + (long)hh*offHB + (long)blockIdx.x*64*ldb;

    const int lRow = tid >> 2;           // 0..63
    const int lCol = (tid & 3) * 4;      // 0,4,8,12

    float acc[4][4];
    #pragma unroll
    for (int i = 0; i < 4; i++)
        #pragma unroll
        for (int j = 0; j < 4; j++) acc[i][j] = 0.f;

    for (int k0 = 0; k0 < K; k0 += 16) {
        #pragma unroll
        for (int u = 0; u < 4; u++) {
            As[lCol+u][lRow] = Ab[(long)lRow*lda + k0 + lCol + u];
            Bs[lCol+u][lRow] = Bb[(long)lRow*ldb + k0 + lCol + u];
        }
        __syncthreads();
        #pragma unroll
        for (int kk = 0; kk < 16; kk++) {
            float a[4], b[4];
            #pragma unroll
            for (int i = 0; i < 4; i++) a[i] = As[kk][trow*4+i];
            #pragma unroll
            for (int j = 0; j < 4; j++) b[j] = Bs[kk][tcol*4+j];
            #pragma unroll
            for (int i = 0; i < 4; i++)
                #pragma unroll
                for (int j = 0; j < 4; j++)
                    acc[i][j] += a[i]*b[j];
        }
        __syncthreads();
    }

    float* Cb = C + (long)z*strC;
    #pragma unroll
    for (int i = 0; i < 4; i++) {
        int m = blockIdx.y*64 + trow*4 + i;
        #pragma unroll
        for (int j = 0; j < 4; j++) {
            int n = blockIdx.x*64 + tcol*4 + j;
            float v = acc[i][j] * scale;
            if (MASK == 1) {
                if (tok[bb*tokStride + n] == 0 || n > m) v = -1e9f;
            } else if (MASK == 2) {
                if (tok[bb*tokStride + n] == 0) v = -1e9f;
            }
            Cb[(long)m*N + n] = v;
        }
    }
}

// ---------------------------------------------------------------------
// batched C[z] = A[z] @ B[z] (+ rowBias[m]).  A: MxK (lda), B: KxN (ldb),
// C: MxN (ldc). K arbitrary (guarded). offsets same pattern as above.
// 64x64 tile, BK=16, 256 threads, 4x4 micro.
// ---------------------------------------------------------------------
template<bool ROWBIAS>
__global__ __launch_bounds__(256) void bgemm_abn(
    const float* __restrict__ A, const float* __restrict__ B,
    float* __restrict__ C,
    int M, int N, int K, int lda, int ldb, int ldc,
    long strA, long offHA, long strB, long offHB, long strC, long offHC,
    int Hh, const float* __restrict__ bias)
{
    __shared__ float As[16][64];
    __shared__ float Bs[16][68];
    const int tid = threadIdx.x;
    const int trow = tid / 16, tcol = tid % 16;
    const int z = blockIdx.z;
    const int bb = z / Hh, hh = z % Hh;

    const float* Ab = A + (long)bb*strA + (long)hh*offHA + (long)blockIdx.y*64*lda;
    const float* Bb = B + (long)bb*strB + (long)hh*offHB + (long)blockIdx.x*64;

    const int aRow = tid >> 2;        // 0..63
    const int aCol = (tid & 3) * 4;   // 0..12
    const int bRow = tid >> 4;        // 0..15
    const int bCol = (tid & 15) * 4;  // 0..60

    float acc[4][4];
    #pragma unroll
    for (int i = 0; i < 4; i++)
        #pragma unroll
        for (int j = 0; j < 4; j++) acc[i][j] = 0.f;

    for (int k0 = 0; k0 < K; k0 += 16) {
        #pragma unroll
        for (int u = 0; u < 4; u++) {
            int kk = k0 + aCol + u;
            As[aCol+u][aRow] = (kk < K) ? Ab[(long)aRow*lda + kk] : 0.f;
        }
        {
            int kk = k0 + bRow;
            #pragma unroll
            for (int u = 0; u < 4; u++)
                Bs[bRow][bCol+u] = (kk < K) ? Bb[(long)kk*ldb + bCol + u] : 0.f;
        }
        __syncthreads();
        #pragma unroll
        for (int kk = 0; kk < 16; kk++) {
            float a[4], b[4];
            #pragma unroll
            for (int i = 0; i < 4; i++) a[i] = As[kk][trow*4+i];
            #pragma unroll
            for (int j = 0; j < 4; j++) b[j] = Bs[kk][tcol*4+j];
            #pragma unroll
            for (int i = 0; i < 4; i++)
                #pragma unroll
                for (int j = 0; j < 4; j++)
                    acc[i][j] += a[i]*b[j];
        }
        __syncthreads();
    }

    float* Cb = C + (long)bb*strC + (long)hh*offHC;
    #pragma unroll
    for (int i = 0; i < 4; i++) {
        int m = blockIdx.y*64 + trow*4 + i;
        float rb = ROWBIAS ? bias[m] : 0.f;
        #pragma unroll
        for (int j = 0; j < 4; j++) {
            int n = blockIdx.x*64 + tcol*4 + j;
            Cb[(long)m*ldc + n] = acc[i][j] + rb;
        }
    }
}

// softmax over rows of length 256 (in place). blockIdx.x = row, 256 threads.
__global__ __launch_bounds__(256) void softmax_rows(float* __restrict__ data)
{
    float* row = data + (long)blockIdx.x * 256;
    int t = threadIdx.x;
    __shared__ float red[256];
    float v = row[t];
    red[t] = v; __syncthreads();
    for (int s = 128; s > 0; s >>= 1) { if (t < s) red[t] = fmaxf(red[t], red[t+s]); __syncthreads(); }
    float m = red[0]; __syncthreads();
    float e = __expf(v - m);
    red[t] = e; __syncthreads();
    for (int s = 128; s > 0; s >>= 1) { if (t < s) red[t] += red[t+s]; __syncthreads(); }
    row[t] = e / red[0];
}

// out = LayerNorm(a + b) * g + beta.  D=512, 256 threads, row per block.
// g/beta may be null (=> 1 / 0).  out may alias a or b.
__global__ __launch_bounds__(256) void add_ln(
    const float* __restrict__ a, const float* __restrict__ b,
    float* __restrict__ out, const float* __restrict__ g,
    const float* __restrict__ beta)
{
    long off = (long)blockIdx.x * DD;
    int t = threadIdx.x;
    float v0 = a[off + t] + b[off + t];
    float v1 = a[off + t + 256] + b[off + t + 256];
    __shared__ float red[256];
    red[t] = v0 + v1; __syncthreads();
    for (int s = 128; s > 0; s >>= 1) { if (t < s) red[t] += red[t+s]; __syncthreads(); }
    float mu = red[0] * (1.f/DD); __syncthreads();
    float d0 = v0 - mu, d1 = v1 - mu;
    red[t] = d0*d0 + d1*d1; __syncthreads();
    for (int s = 128; s > 0; s >>= 1) { if (t < s) red[t] += red[t+s]; __syncthreads(); }
    float rstd = rsqrtf(red[0] * (1.f/DD) + 1e-5f);
    float g0 = g ? g[t] : 1.f,       g1 = g ? g[t+256] : 1.f;
    float b0 = beta ? beta[t] : 0.f, b1 = beta ? beta[t+256] : 0.f;
    out[off + t]       = d0 * rstd * g0 + b0;
    out[off + t + 256] = d1 * rstd * g1 + b1;
}

// x[b,t,:] = emb[dec[b,t],:] + PE(t,:)
__global__ void embed_pe(const int* __restrict__ dec,
                         const float* __restrict__ emb,
                         float* __restrict__ x)
{
    long idx = (long)blockIdx.x * blockDim.x + threadIdx.x;
    if (idx >= (long)BT*DD) return;
    int d  = (int)(idx % DD);
    long bt = idx / DD;
    int t  = (int)(bt % TT);
    int tokidx = dec[bt];
    int d2 = d & ~1;
    float div = expf(-logf(10000.f) * (float)d2 / (float)DD);
    float ang = (float)t * div;
    float pe = (d & 1) ? cosf(ang) : sinf(ang);
    x[idx] = emb[(long)tokidx*DD + d] + pe;
}

// out[i] = a[i] + bias[i % D] + c[i]
__global__ void add3(const float* __restrict__ a, const float* __restrict__ bias,
                     const float* __restrict__ c, float* __restrict__ out, long n)
{
    long i = (long)blockIdx.x * blockDim.x + threadIdx.x;
    if (i >= n) return;
    out[i] = a[i] + bias[i % DD] + c[i];
}

__global__ void copyk(const float* __restrict__ src, float* __restrict__ dst, long n)
{
    long i = (long)blockIdx.x * blockDim.x + threadIdx.x;
    if (i < n) dst[i] = src[i];
}

// ---------------------------------------------------------------------
extern "C" void kernel_launch(void* const* d_in, const int* in_sizes, int n_in,
                              void* d_out, int out_size)
{
    const int*   dec     = (const int*)  d_in[0];
    const int*   enc     = (const int*)  d_in[1];
    const float* enc_out = (const float*)d_in[2];
    const float* ast_out = (const float*)d_in[3];
    const float* src_emb = (const float*)d_in[4];
    const float* ast_emb = (const float*)d_in[5];
    /* match_rela d_in[6] unused */
    const float* emb     = (const float*)d_in[7];
    const float* attn_W  = (const float*)d_in[8];
    const float* ln_g    = (const float*)d_in[9];
    const float* ln_b    = (const float*)d_in[10];
    const float* W1      = (const float*)d_in[11];
    const float* W2      = (const float*)d_in[12];
    const float* conv_w  = (const float*)d_in[13];
    const float* conv_b  = (const float*)d_in[14];
    const float* mffnW   = (const float*)d_in[15];
    const float* mffnb   = (const float*)d_in[16];
    float* out = (float*)d_out;

    float *x,*t,*q,*k,*v,*c,*h,*multi,*ast1,*aste,*mm,*mmctx;
    cudaGetSymbolAddress((void**)&x,     g_x);
    cudaGetSymbolAddress((void**)&t,     g_t);
    cudaGetSymbolAddress((void**)&q,     g_q);
    cudaGetSymbolAddress((void**)&k,     g_k);
    cudaGetSymbolAddress((void**)&v,     g_v);
    cudaGetSymbolAddress((void**)&c,     g_c);
    cudaGetSymbolAddress((void**)&h,     g_h);
    cudaGetSymbolAddress((void**)&multi, g_multi);
    cudaGetSymbolAddress((void**)&ast1,  g_ast1);
    cudaGetSymbolAddress((void**)&aste,  g_aste);
    cudaGetSymbolAddress((void**)&mm,    g_mm);
    cudaGetSymbolAddress((void**)&mmctx, g_mmctx);

    // ---------------- multi_model preamble ----------------
    // ast1 = conv_w @ ast_outputs + conv_b[s]; ast_e1 likewise
    {
        dim3 grid(DD/64, SS/64, BB);
        bgemm_abn<true><<<grid, 256>>>(conv_w, ast_out, ast1,
            SS, DD, NA, NA, DD, DD,
            0L, 0L, (long)NA*DD, 0L, (long)SS*DD, 0L, 1, conv_b);
        bgemm_abn<true><<<grid, 256>>>(conv_w, ast_emb, aste,
            SS, DD, NA, NA, DD, DD,
            0L, 0L, (long)NA*DD, 0L, (long)SS*DD, 0L, 1, conv_b);
    }
    // mm_scores = ast1 @ enc_out^T / 8 ; softmax ; mm_ctx = P @ enc_out
    {
        dim3 grid(SS/64, SS/64, BB);
        bgemm_abT<0><<<grid, 256>>>(ast1, enc_out, mm,
            SS, SS, DD, DD, DD,
            (long)SS*DD, 0L, (long)SS*DD, 0L, (long)SS*SS,
            1, 0.125f, nullptr, 0);
        softmax_rows<<<BB*SS, 256>>>(mm);
        dim3 grid2(DD/64, SS/64, BB);
        bgemm_abn<false><<<grid2, 256>>>(mm, enc_out, mmctx,
            SS, DD, SS, SS, DD, DD,
            (long)SS*SS, 0L, (long)SS*DD, 0L, (long)SS*DD, 0L, 1, nullptr);
    }
    // multi_out = src_embed @ W_top + ast_e1 @ W_bot + b + mm_ctx
    {
        dim3 grid(DD/128, BT/128);
        sgemm_k<false,false><<<grid, 256>>>(src_emb, mffnW,            t, BT, DD, DD);
        sgemm_k<false,true ><<<grid, 256>>>(aste,    mffnW + DD*DD,    t, BT, DD, DD);
        long n = (long)BB*SS*DD;
        add3<<<(int)((n + 255)/256), 256>>>(t, mffnb, mmctx, multi, n);
    }
    // x = emb[dec] + PE
    embed_pe<<<(BT*DD + 255)/256, 256>>>(dec, emb, x);

    // ---------------- decoder layers ----------------
    dim3 gProj(DD/128, BT/128);          // 4096x512x512 projections
    dim3 gF1(DFF/128, BT/128);
    dim3 gScore(TT/64, TT/64, BB*HH);
    dim3 gCtx(1, TT/64, BB*HH);

    for (int l = 0; l < LL; l++) {
        for (int a = 0; a < 3; a++) {
            const float* W = attn_W + ((long)(l*3 + a) * 4) * DD * DD;
            const float* Wq = W;
            const float* Wk = W + (long)DD*DD;
            const float* Wv = W + 2L*DD*DD;
            const float* Wo = W + 3L*DD*DD;
            const float* xk = (a == 0) ? x : (a == 1 ? enc_out : multi);

            sgemm_k<false,false><<<gProj, 256>>>(x,  Wq, q, BT, DD, DD);
            sgemm_k<false,false><<<gProj, 256>>>(xk, Wk, k, BT, DD, DD);
            sgemm_k<false,false><<<gProj, 256>>>(xk, Wv, v, BT, DD, DD);

            long attnBase = (a == 0 ? SELF_OFF : (a == 1 ? ENC_OFF : AST_OFF))
                            + (long)l * BHTT;
            float* P = out + attnBase;

            if (a == 0)
                bgemm_abT<1><<<gScore, 256>>>(q, k, P,
                    TT, TT, DKK, DD, DD,
                    (long)TT*DD, 64L, (long)TT*DD, 64L, (long)TT*TT,
                    HH, 0.125f, dec, TT);
            else if (a == 1)
                bgemm_abT<2><<<gScore, 256>>>(q, k, P,
                    TT, TT, DKK, DD, DD,
                    (long)TT*DD, 64L, (long)TT*DD, 64L, (long)TT*TT,
                    HH, 0.125f, enc, SS);
            else
                bgemm_abT<0><<<gScore, 256>>>(q, k, P,
                    TT, TT, DKK, DD, DD,
                    (long)TT*DD, 64L, (long)TT*DD, 64L, (long)TT*TT,
                    HH, 0.125f, nullptr, 0);

            softmax_rows<<<BB*HH*TT, 256>>>(P);

            // ctx[b,t,h*64:] = P[b,h] @ V[b,:,h*64:]
            bgemm_abn<false><<<gCtx, 256>>>(P, v, c,
                TT, DKK, TT, TT, DD, DD,
                (long)HH*TT*TT, (long)TT*TT, (long)TT*DD, 64L,
                (long)TT*DD, 64L, HH, nullptr);

            sgemm_k<false,false><<<gProj, 256>>>(c, Wo, t, BT, DD, DD);
            add_ln<<<BT, 256>>>(t, x, x,
                ln_g + (long)(l*3 + a)*DD, ln_b + (long)(l*3 + a)*DD);
        }
        // FFN
        sgemm_k<true ,false><<<gF1,   256>>>(x, W1 + (long)l*DD*DFF, h, BT, DFF, DD);
        sgemm_k<false,false><<<gProj, 256>>>(h, W2 + (long)l*DFF*DD, t, BT, DD, DFF);
        add_ln<<<BT, 256>>>(t, x, x, nullptr, nullptr);
    }

    // final x -> d_out[0:BT*D]
    copyk<<<(BT*DD + 255)/256, 256>>>(x, out + X_OFF, (long)BT*DD);
}

// round 2
// speedup vs baseline: 3.1798x; 3.1798x over previous
#include <cuda_runtime.h>
#include <math.h>

// Problem dims
#define BB 16
#define TT 256
#define SS 256
#define NA 300
#define DD 512
#define HH 8
#define DKK 64
#define DFF 2048
#define LL 6

#define BT (BB*TT)                 // 4096
#define BHTT ((long)BB*HH*TT*TT)   // 8388608

// d_out layout (floats): x | self_attns | enc_attns | ast_attns
#define SELF_OFF 2097152L
#define ENC_OFF  (SELF_OFF + (long)LL*BHTT)
#define AST_OFF  (ENC_OFF  + (long)LL*BHTT)

// ------------- scratch -------------
__device__ float g_x[BT*DD];
__device__ float g_t[BT*DD];
__device__ float g_q[BT*DD];
__device__ float g_k[BT*DD];
__device__ float g_v[BT*DD];
__device__ float g_c[BT*DD];
__device__ float g_h[BT*DFF];
__device__ float g_multi[BB*SS*DD];
__device__ float g_ast1[BB*SS*DD];
__device__ float g_aste[BB*SS*DD];
__device__ float g_mm[BB*SS*SS];
__device__ float g_mmctx[BB*SS*DD];

// ------------- tf32 helpers -------------
__device__ __forceinline__ unsigned f2tf(float x) {
    unsigned u; asm("cvt.rna.tf32.f32 %0, %1;" : "=r"(u) : "f"(x)); return u;
}
__device__ __forceinline__ void mma_tf32(float* d,
    unsigned a0, unsigned a1, unsigned a2, unsigned a3,
    unsigned b0, unsigned b1)
{
    asm volatile(
        "mma.sync.aligned.m16n8k8.row.col.f32.tf32.tf32.f32 "
        "{%0,%1,%2,%3},{%4,%5,%6,%7},{%8,%9},{%0,%1,%2,%3};\n"
        : "+f"(d[0]), "+f"(d[1]), "+f"(d[2]), "+f"(d[3])
        : "r"(a0), "r"(a1), "r"(a2), "r"(a3), "r"(b0), "r"(b1));
}

// ---------------------------------------------------------------------
// gemm_tf32: C[M,N] = A[M,K] @ B[K,N], row-major. M%128==0, N%128==0, K%32==0.
// 128x128x32 tile, 256 threads, warps 2x4, warp-tile 64x32, m16n8k8 tf32.
// ---------------------------------------------------------------------
template<bool RELU, bool ACC>
__global__ __launch_bounds__(256) void gemm_tf32(
    const float* __restrict__ A, const float* __restrict__ B,
    float* __restrict__ C, int M, int N, int K)
{
    __shared__ unsigned As[128*36];   // As[m][k], stride 36
    __shared__ unsigned Bs[32*136];   // Bs[k][n], stride 136
    const int tid = threadIdx.x, warp = tid >> 5, lane = tid & 31;
    const int g = lane >> 2, tg = lane & 3;
    const int wr = warp >> 2, wc = warp & 3;   // wr:0..1 (64 rows), wc:0..3 (32 cols)

    const float* Ab = A + (long)blockIdx.y * 128 * K;
    const float* Bb = B + (long)blockIdx.x * 128;

    float acc[16][4];
    #pragma unroll
    for (int i = 0; i < 16; i++) { acc[i][0]=0.f; acc[i][1]=0.f; acc[i][2]=0.f; acc[i][3]=0.f; }

    for (int k0 = 0; k0 < K; k0 += 32) {
        #pragma unroll
        for (int p = 0; p < 4; p++) {       // A: 128x32 = 1024 float4
            int idx = tid + p*256;
            int r = idx >> 3, c4 = idx & 7;
            float4 v = *reinterpret_cast<const float4*>(Ab + (long)r*K + k0 + c4*4);
            unsigned* d = &As[r*36 + c4*4];
            d[0]=f2tf(v.x); d[1]=f2tf(v.y); d[2]=f2tf(v.z); d[3]=f2tf(v.w);
        }
        #pragma unroll
        for (int p = 0; p < 4; p++) {       // B: 32x128 = 1024 float4
            int idx = tid + p*256;
            int r = idx >> 5, c4 = idx & 31;
            float4 v = *reinterpret_cast<const float4*>(Bb + (long)(k0 + r)*N + c4*4);
            unsigned* d = &Bs[r*136 + c4*4];
            d[0]=f2tf(v.x); d[1]=f2tf(v.y); d[2]=f2tf(v.z); d[3]=f2tf(v.w);
        }
        __syncthreads();
        #pragma unroll
        for (int ks = 0; ks < 4; ks++) {
            const int kk = ks * 8;
            unsigned a[4][4], b[4][2];
            #pragma unroll
            for (int mi = 0; mi < 4; mi++) {
                int mb = wr*64 + mi*16;
                a[mi][0] = As[(mb+g  )*36 + kk + tg];
                a[mi][1] = As[(mb+g+8)*36 + kk + tg];
                a[mi][2] = As[(mb+g  )*36 + kk + tg + 4];
                a[mi][3] = As[(mb+g+8)*36 + kk + tg + 4];
            }
            #pragma unroll
            for (int nj = 0; nj < 4; nj++) {
                int nb = wc*32 + nj*8;
                b[nj][0] = Bs[(kk+tg  )*136 + nb + g];
                b[nj][1] = Bs[(kk+tg+4)*136 + nb + g];
            }
            #pragma unroll
            for (int mi = 0; mi < 4; mi++)
                #pragma unroll
                for (int nj = 0; nj < 4; nj++)
                    mma_tf32(acc[mi*4+nj], a[mi][0],a[mi][1],a[mi][2],a[mi][3],
                             b[nj][0], b[nj][1]);
        }
        __syncthreads();
    }

    // epilogue
    #pragma unroll
    for (int mi = 0; mi < 4; mi++) {
        #pragma unroll
        for (int nj = 0; nj < 4; nj++) {
            float* d = acc[mi*4+nj];
            int r0 = blockIdx.y*128 + wr*64 + mi*16 + g;
            int col = blockIdx.x*128 + wc*32 + nj*8 + tg*2;
            float2 v0 = make_float2(d[0], d[1]);
            float2 v1 = make_float2(d[2], d[3]);
            float2* p0 = reinterpret_cast<float2*>(C + (long)r0*N + col);
            float2* p1 = reinterpret_cast<float2*>(C + (long)(r0+8)*N + col);
            if (ACC) { float2 o0 = *p0, o1 = *p1; v0.x+=o0.x; v0.y+=o0.y; v1.x+=o1.x; v1.y+=o1.y; }
            if (RELU) { v0.x=fmaxf(v0.x,0.f); v0.y=fmaxf(v0.y,0.f); v1.x=fmaxf(v1.x,0.f); v1.y=fmaxf(v1.y,0.f); }
            *p0 = v0; *p1 = v1;
        }
    }
}

// ---------------------------------------------------------------------
// attn_score_softmax: per block computes S = scale * Q @ K^T over a 64-row
// x 256-col span (the full softmax width), applies mask, softmax, writes P.
// Kdim: contraction length (chunked by 64). 256 threads, warps 2x4,
// warp-tile 32x64. P row length fixed at 256; strC fixed at 65536.
// MASK: 0 none, 1 pad|causal, 2 pad.
// ---------------------------------------------------------------------
template<int MASK>
__global__ __launch_bounds__(256) void attn_score_softmax(
    const float* __restrict__ Q, const float* __restrict__ Km,
    float* __restrict__ P, int Kdim, int lda, int ldb,
    long strA, long offHA, long strB, long offHB,
    int Hh, float scale, const int* __restrict__ tok, int tokStride)
{
    extern __shared__ unsigned sm[];
    unsigned* Qs = sm;            // [64][68]
    unsigned* Ks = sm + 64*68;    // [256][68]  (stored as [n][k])
    __shared__ float red[64*4];

    const int tid = threadIdx.x, warp = tid >> 5, lane = tid & 31;
    const int g = lane >> 2, tg = lane & 3;
    const int wr = warp >> 2, wc = warp & 3;  // wr:0..1 (32 rows), wc:0..3 (64 cols)
    const int z = blockIdx.y;
    const int bb = z / Hh, hh = z - bb*Hh;
    const int rowTile = blockIdx.x;

    const float* Qb = Q + (long)bb*strA + (long)hh*offHA + (long)rowTile*64*lda;
    const float* Kb = Km + (long)bb*strB + (long)hh*offHB;

    float acc[16][4];
    #pragma unroll
    for (int i = 0; i < 16; i++) { acc[i][0]=0.f; acc[i][1]=0.f; acc[i][2]=0.f; acc[i][3]=0.f; }

    for (int k0 = 0; k0 < Kdim; k0 += 64) {
        #pragma unroll
        for (int p = 0; p < 4; p++) {          // Q: 64x64 = 1024 f4
            int idx = tid + p*256;
            int r = idx >> 4, c4 = idx & 15;
            float4 v = *reinterpret_cast<const float4*>(Qb + (long)r*lda + k0 + c4*4);
            unsigned* d = &Qs[r*68 + c4*4];
            d[0]=f2tf(v.x); d[1]=f2tf(v.y); d[2]=f2tf(v.z); d[3]=f2tf(v.w);
        }
        #pragma unroll
        for (int p = 0; p < 16; p++) {         // K: 256x64 = 4096 f4
            int idx = tid + p*256;
            int r = idx >> 4, c4 = idx & 15;
            float4 v = *reinterpret_cast<const float4*>(Kb + (long)r*ldb + k0 + c4*4);
            unsigned* d = &Ks[r*68 + c4*4];
            d[0]=f2tf(v.x); d[1]=f2tf(v.y); d[2]=f2tf(v.z); d[3]=f2tf(v.w);
        }
        __syncthreads();
        #pragma unroll
        for (int ks = 0; ks < 8; ks++) {
            const int kk = ks * 8;
            unsigned a[2][4], b[8][2];
            #pragma unroll
            for (int mi = 0; mi < 2; mi++) {
                int mb = wr*32 + mi*16;
                a[mi][0] = Qs[(mb+g  )*68 + kk + tg];
                a[mi][1] = Qs[(mb+g+8)*68 + kk + tg];
                a[mi][2] = Qs[(mb+g  )*68 + kk + tg + 4];
                a[mi][3] = Qs[(mb+g+8)*68 + kk + tg + 4];
            }
            #pragma unroll
            for (int nj = 0; nj < 8; nj++) {
                int nb = wc*64 + nj*8;
                b[nj][0] = Ks[(nb+g)*68 + kk + tg];
                b[nj][1] = Ks[(nb+g)*68 + kk + tg + 4];
            }
            #pragma unroll
            for (int mi = 0; mi < 2; mi++)
                #pragma unroll
                for (int nj = 0; nj < 8; nj++)
                    mma_tf32(acc[mi*8+nj], a[mi][0],a[mi][1],a[mi][2],a[mi][3],
                             b[nj][0], b[nj][1]);
        }
        __syncthreads();
    }

    // ---- scale + mask ----
    const int rowBase = rowTile * 64;
    #pragma unroll
    for (int mi = 0; mi < 2; mi++) {
        #pragma unroll
        for (int nj = 0; nj < 8; nj++) {
            float* d = acc[mi*8+nj];
            int col = wc*64 + nj*8 + tg*2;
            int lr0 = wr*32 + mi*16 + g;
            #pragma unroll
            for (int c = 0; c < 4; c++) {
                int gcol = col + (c & 1);
                int grow = rowBase + lr0 + ((c >> 1) * 8);
                float v = d[c] * scale;
                if (MASK == 1) {
                    if (tok[bb*tokStride + gcol] == 0 || gcol > grow) v = -1e9f;
                } else if (MASK == 2) {
                    if (tok[bb*tokStride + gcol] == 0) v = -1e9f;
                }
                d[c] = v;
            }
        }
    }

    // ---- softmax over full 256-wide rows ----
    // thread owns 4 local rows: wr*32 + mi*16 + g (+8), 16 cols each
    float rmax[4];
    #pragma unroll
    for (int mi = 0; mi < 2; mi++) {
        float m0 = -1e30f, m1 = -1e30f;
        #pragma unroll
        for (int nj = 0; nj < 8; nj++) {
            float* d = acc[mi*8+nj];
            m0 = fmaxf(m0, fmaxf(d[0], d[1]));
            m1 = fmaxf(m1, fmaxf(d[2], d[3]));
        }
        rmax[mi*2+0] = m0; rmax[mi*2+1] = m1;
    }
    #pragma unroll
    for (int i = 0; i < 4; i++) {
        rmax[i] = fmaxf(rmax[i], __shfl_xor_sync(0xffffffffu, rmax[i], 1));
        rmax[i] = fmaxf(rmax[i], __shfl_xor_sync(0xffffffffu, rmax[i], 2));
    }
    if (tg == 0) {
        #pragma unroll
        for (int mi = 0; mi < 2; mi++) {
            red[(wr*32 + mi*16 + g    )*4 + wc] = rmax[mi*2+0];
            red[(wr*32 + mi*16 + g + 8)*4 + wc] = rmax[mi*2+1];
        }
    }
    __syncthreads();
    float fmax4[4];
    #pragma unroll
    for (int mi = 0; mi < 2; mi++) {
        int r0 = wr*32 + mi*16 + g, r1 = r0 + 8;
        fmax4[mi*2+0] = fmaxf(fmaxf(red[r0*4+0], red[r0*4+1]), fmaxf(red[r0*4+2], red[r0*4+3]));
        fmax4[mi*2+1] = fmaxf(fmaxf(red[r1*4+0], red[r1*4+1]), fmaxf(red[r1*4+2], red[r1*4+3]));
    }
    __syncthreads();

    float rsum[4] = {0.f, 0.f, 0.f, 0.f};
    #pragma unroll
    for (int mi = 0; mi < 2; mi++) {
        #pragma unroll
        for (int nj = 0; nj < 8; nj++) {
            float* d = acc[mi*8+nj];
            d[0] = __expf(d[0] - fmax4[mi*2+0]);
            d[1] = __expf(d[1] - fmax4[mi*2+0]);
            d[2] = __expf(d[2] - fmax4[mi*2+1]);
            d[3] = __expf(d[3] - fmax4[mi*2+1]);
            rsum[mi*2+0] += d[0] + d[1];
            rsum[mi*2+1] += d[2] + d[3];
        }
    }
    #pragma unroll
    for (int i = 0; i < 4; i++) {
        rsum[i] += __shfl_xor_sync(0xffffffffu, rsum[i], 1);
        rsum[i] += __shfl_xor_sync(0xffffffffu, rsum[i], 2);
    }
    if (tg == 0) {
        #pragma unroll
        for (int mi = 0; mi < 2; mi++) {
            red[(wr*32 + mi*16 + g    )*4 + wc] = rsum[mi*2+0];
            red[(wr*32 + mi*16 + g + 8)*4 + wc] = rsum[mi*2+1];
        }
    }
    __syncthreads();
    float rinv[4];
    #pragma unroll
    for (int mi = 0; mi < 2; mi++) {
        int r0 = wr*32 + mi*16 + g, r1 = r0 + 8;
        rinv[mi*2+0] = 1.f / (red[r0*4+0] + red[r0*4+1] + red[r0*4+2] + red[r0*4+3]);
        rinv[mi*2+1] = 1.f / (red[r1*4+0] + red[r1*4+1] + red[r1*4+2] + red[r1*4+3]);
    }

    float* Pb = P + (long)z * 65536L + (long)rowBase * 256;
    #pragma unroll
    for (int mi = 0; mi < 2; mi++) {
        #pragma unroll
        for (int nj = 0; nj < 8; nj++) {
            float* d = acc[mi*8+nj];
            int col = wc*64 + nj*8 + tg*2;
            int r0 = wr*32 + mi*16 + g;
            *reinterpret_cast<float2*>(Pb + (long)r0*256 + col) =
                make_float2(d[0]*rinv[mi*2+0], d[1]*rinv[mi*2+0]);
            *reinterpret_cast<float2*>(Pb + (long)(r0+8)*256 + col) =
                make_float2(d[2]*rinv[mi*2+1], d[3]*rinv[mi*2+1]);
        }
    }
}

// ---------------------------------------------------------------------
// bgemm_tf32: batched C[z] = A[z] @ B[z] (+ rowBias). A row-major MxK,
// B row-major KxN. 128x64x32 tiles, 256 threads, warps 4x2, warp 32x32.
// M%128==0, N%64==0, K arbitrary (guarded).
// Aoff=(z/Hh)*strA+(z%Hh)*offHA, same for B, C.
// ---------------------------------------------------------------------
template<bool ROWBIAS>
__global__ __launch_bounds__(256) void bgemm_tf32(
    const float* __restrict__ A, const float* __restrict__ B,
    float* __restrict__ C, int M, int N, int K,
    int lda, int ldb, int ldc,
    long strA, long offHA, long strB, long offHB, long strC, long offHC,
    int Hh, const float* __restrict__ bias)
{
    __shared__ unsigned As[128*36];
    __shared__ unsigned Bs[32*72];
    const int tid = threadIdx.x, warp = tid >> 5, lane = tid & 31;
    const int g = lane >> 2, tg = lane & 3;
    const int wr = warp >> 1, wc = warp & 1;   // wr:0..3 (32 rows), wc:0..1 (32 cols)
    const int z = blockIdx.z;
    const int bb = z / Hh, hh = z - bb*Hh;

    const float* Ab = A + (long)bb*strA + (long)hh*offHA + (long)blockIdx.y*128*lda;
    const float* Bb = B + (long)bb*strB + (long)hh*offHB + (long)blockIdx.x*64;

    float acc[8][4];
    #pragma unroll
    for (int i = 0; i < 8; i++) { acc[i][0]=0.f; acc[i][1]=0.f; acc[i][2]=0.f; acc[i][3]=0.f; }

    for (int k0 = 0; k0 < K; k0 += 32) {
        if (k0 + 32 <= K && (lda & 3) == 0) {
            #pragma unroll
            for (int p = 0; p < 4; p++) {
                int idx = tid + p*256;
                int r = idx >> 3, c4 = idx & 7;
                float4 v = *reinterpret_cast<const float4*>(Ab + (long)r*lda + k0 + c4*4);
                unsigned* d = &As[r*36 + c4*4];
                d[0]=f2tf(v.x); d[1]=f2tf(v.y); d[2]=f2tf(v.z); d[3]=f2tf(v.w);
            }
        } else {
            #pragma unroll
            for (int p = 0; p < 16; p++) {
                int idx = tid + p*256;
                int r = idx >> 5, c = idx & 31;
                float v = (k0 + c < K) ? Ab[(long)r*lda + k0 + c] : 0.f;
                As[r*36 + c] = f2tf(v);
            }
        }
        #pragma unroll
        for (int p = 0; p < 2; p++) {
            int idx = tid + p*256;
            int r = idx >> 4, c4 = idx & 15;
            float4 v;
            if (k0 + r < K)
                v = *reinterpret_cast<const float4*>(Bb + (long)(k0 + r)*ldb + c4*4);
            else
                v = make_float4(0.f, 0.f, 0.f, 0.f);
            unsigned* d = &Bs[r*72 + c4*4];
            d[0]=f2tf(v.x); d[1]=f2tf(v.y); d[2]=f2tf(v.z); d[3]=f2tf(v.w);
        }
        __syncthreads();
        #pragma unroll
        for (int ks = 0; ks < 4; ks++) {
            const int kk = ks * 8;
            unsigned a[2][4], b[4][2];
            #pragma unroll
            for (int mi = 0; mi < 2; mi++) {
                int mb = wr*32 + mi*16;
                a[mi][0] = As[(mb+g  )*36 + kk + tg];
                a[mi][1] = As[(mb+g+8)*36 + kk + tg];
                a[mi][2] = As[(mb+g  )*36 + kk + tg + 4];
                a[mi][3] = As[(mb+g+8)*36 + kk + tg + 4];
            }
            #pragma unroll
            for (int nj = 0; nj < 4; nj++) {
                int nb = wc*32 + nj*8;
                b[nj][0] = Bs[(kk+tg  )*72 + nb + g];
                b[nj][1] = Bs[(kk+tg+4)*72 + nb + g];
            }
            #pragma unroll
            for (int mi = 0; mi < 2; mi++)
                #pragma unroll
                for (int nj = 0; nj < 4; nj++)
                    mma_tf32(acc[mi*4+nj], a[mi][0],a[mi][1],a[mi][2],a[mi][3],
                             b[nj][0], b[nj][1]);
        }
        __syncthreads();
    }

    float* Cb = C + (long)bb*strC + (long)hh*offHC;
    #pragma unroll
    for (int mi = 0; mi < 2; mi++) {
        #pragma unroll
        for (int nj = 0; nj < 4; nj++) {
            float* d = acc[mi*4+nj];
            int r0 = blockIdx.y*128 + wr*32 + mi*16 + g;
            int col = blockIdx.x*64 + wc*32 + nj*8 + tg*2;
            float b0 = ROWBIAS ? bias[r0] : 0.f;
            float b1 = ROWBIAS ? bias[r0+8] : 0.f;
            *reinterpret_cast<float2*>(Cb + (long)r0*ldc + col) =
                make_float2(d[0]+b0, d[1]+b0);
            *reinterpret_cast<float2*>(Cb + (long)(r0+8)*ldc + col) =
                make_float2(d[2]+b1, d[3]+b1);
        }
    }
}

// ---------------------------------------------------------------------
// out = LayerNorm(a + b) * g + beta. D=512, 256 threads/row.
__global__ __launch_bounds__(256) void add_ln(
    const float* __restrict__ a, const float* __restrict__ b,
    float* __restrict__ out, const float* __restrict__ g,
    const float* __restrict__ beta)
{
    long off = (long)blockIdx.x * DD;
    int t = threadIdx.x;
    float v0 = a[off + t] + b[off + t];
    float v1 = a[off + t + 256] + b[off + t + 256];
    __shared__ float red[256];
    red[t] = v0 + v1; __syncthreads();
    for (int s = 128; s > 0; s >>= 1) { if (t < s) red[t] += red[t+s]; __syncthreads(); }
    float mu = red[0] * (1.f/DD); __syncthreads();
    float d0 = v0 - mu, d1 = v1 - mu;
    red[t] = d0*d0 + d1*d1; __syncthreads();
    for (int s = 128; s > 0; s >>= 1) { if (t < s) red[t] += red[t+s]; __syncthreads(); }
    float rstd = rsqrtf(red[0] * (1.f/DD) + 1e-5f);
    float g0 = g ? g[t] : 1.f,       g1 = g ? g[t+256] : 1.f;
    float b0 = beta ? beta[t] : 0.f, b1 = beta ? beta[t+256] : 0.f;
    out[off + t]       = d0 * rstd * g0 + b0;
    out[off + t + 256] = d1 * rstd * g1 + b1;
}

__global__ void embed_pe(const int* __restrict__ dec,
                         const float* __restrict__ emb,
                         float* __restrict__ x)
{
    long idx = (long)blockIdx.x * blockDim.x + threadIdx.x;
    if (idx >= (long)BT*DD) return;
    int d  = (int)(idx % DD);
    long bt = idx / DD;
    int t  = (int)(bt % TT);
    int tokidx = dec[bt];
    int d2 = d & ~1;
    float div = expf(-logf(10000.f) * (float)d2 / (float)DD);
    float ang = (float)t * div;
    float pe = (d & 1) ? cosf(ang) : sinf(ang);
    x[idx] = emb[(long)tokidx*DD + d] + pe;
}

__global__ void add3(const float* __restrict__ a, const float* __restrict__ bias,
                     const float* __restrict__ c, float* __restrict__ out, long n)
{
    long i = (long)blockIdx.x * blockDim.x + threadIdx.x;
    if (i >= n) return;
    out[i] = a[i] + bias[i % DD] + c[i];
}

__global__ void copyk(const float* __restrict__ src, float* __restrict__ dst, long n)
{
    long i = (long)blockIdx.x * blockDim.x + threadIdx.x;
    if (i < n) dst[i] = src[i];
}

// ---------------------------------------------------------------------
extern "C" void kernel_launch(void* const* d_in, const int* in_sizes, int n_in,
                              void* d_out, int out_size)
{
    const int*   dec     = (const int*)  d_in[0];
    const int*   enc     = (const int*)  d_in[1];
    const float* enc_out = (const float*)d_in[2];
    const float* ast_out = (const float*)d_in[3];
    const float* src_emb = (const float*)d_in[4];
    const float* ast_emb = (const float*)d_in[5];
    const float* emb     = (const float*)d_in[7];
    const float* attn_W  = (const float*)d_in[8];
    const float* ln_g    = (const float*)d_in[9];
    const float* ln_b    = (const float*)d_in[10];
    const float* W1      = (const float*)d_in[11];
    const float* W2      = (const float*)d_in[12];
    const float* conv_w  = (const float*)d_in[13];
    const float* conv_b  = (const float*)d_in[14];
    const float* mffnW   = (const float*)d_in[15];
    const float* mffnb   = (const float*)d_in[16];
    float* out = (float*)d_out;

    float *x,*t,*q,*k,*v,*c,*h,*multi,*ast1,*aste,*mm,*mmctx;
    cudaGetSymbolAddress((void**)&x,     g_x);
    cudaGetSymbolAddress((void**)&t,     g_t);
    cudaGetSymbolAddress((void**)&q,     g_q);
    cudaGetSymbolAddress((void**)&k,     g_k);
    cudaGetSymbolAddress((void**)&v,     g_v);
    cudaGetSymbolAddress((void**)&c,     g_c);
    cudaGetSymbolAddress((void**)&h,     g_h);
    cudaGetSymbolAddress((void**)&multi, g_multi);
    cudaGetSymbolAddress((void**)&ast1,  g_ast1);
    cudaGetSymbolAddress((void**)&aste,  g_aste);
    cudaGetSymbolAddress((void**)&mm,    g_mm);
    cudaGetSymbolAddress((void**)&mmctx, g_mmctx);

    const int SC_SMEM = (64*68 + 256*68) * 4;   // 87040 bytes
    cudaFuncSetAttribute(attn_score_softmax<0>, cudaFuncAttributeMaxDynamicSharedMemorySize, SC_SMEM);
    cudaFuncSetAttribute(attn_score_softmax<1>, cudaFuncAttributeMaxDynamicSharedMemorySize, SC_SMEM);
    cudaFuncSetAttribute(attn_score_softmax<2>, cudaFuncAttributeMaxDynamicSharedMemorySize, SC_SMEM);

    // ---------------- multi_model preamble ----------------
    {
        dim3 grid(DD/64, SS/128, BB);
        bgemm_tf32<true><<<grid, 256>>>(conv_w, ast_out, ast1,
            SS, DD, NA, NA, DD, DD,
            0L, 0L, (long)NA*DD, 0L, (long)SS*DD, 0L, 1, conv_b);
        bgemm_tf32<true><<<grid, 256>>>(conv_w, ast_emb, aste,
            SS, DD, NA, NA, DD, DD,
            0L, 0L, (long)NA*DD, 0L, (long)SS*DD, 0L, 1, conv_b);
    }
    {
        dim3 gs(SS/64, BB);
        attn_score_softmax<0><<<gs, 256, SC_SMEM>>>(ast1, enc_out, mm,
            DD, DD, DD, (long)SS*DD, 0L, (long)SS*DD, 0L,
            1, 0.125f, nullptr, 0);
        dim3 grid2(DD/64, SS/128, BB);
        bgemm_tf32<false><<<grid2, 256>>>(mm, enc_out, mmctx,
            SS, DD, SS, SS, DD, DD,
            (long)SS*SS, 0L, (long)SS*DD, 0L, (long)SS*DD, 0L, 1, nullptr);
    }
    {
        dim3 grid(DD/128, BT/128);
        gemm_tf32<false,false><<<grid, 256>>>(src_emb, mffnW,         t, BT, DD, DD);
        gemm_tf32<false,true ><<<grid, 256>>>(aste,    mffnW + DD*DD, t, BT, DD, DD);
        long n = (long)BB*SS*DD;
        add3<<<(int)((n + 255)/256), 256>>>(t, mffnb, mmctx, multi, n);
    }
    embed_pe<<<(BT*DD + 255)/256, 256>>>(dec, emb, x);

    // ---------------- decoder layers ----------------
    dim3 gProj(DD/128, BT/128);
    dim3 gF1(DFF/128, BT/128);
    dim3 gScore(TT/64, BB*HH);
    dim3 gCtx(1, TT/128, BB*HH);

    for (int l = 0; l < LL; l++) {
        for (int a = 0; a < 3; a++) {
            const float* W = attn_W + ((long)(l*3 + a) * 4) * DD * DD;
            const float* Wq = W;
            const float* Wk = W + (long)DD*DD;
            const float* Wv = W + 2L*DD*DD;
            const float* Wo = W + 3L*DD*DD;
            const float* xk = (a == 0) ? x : (a == 1 ? enc_out : multi);

            gemm_tf32<false,false><<<gProj, 256>>>(x,  Wq, q, BT, DD, DD);
            gemm_tf32<false,false><<<gProj, 256>>>(xk, Wk, k, BT, DD, DD);
            gemm_tf32<false,false><<<gProj, 256>>>(xk, Wv, v, BT, DD, DD);

            long attnBase = (a == 0 ? SELF_OFF : (a == 1 ? ENC_OFF : AST_OFF))
                            + (long)l * BHTT;
            float* P = out + attnBase;

            if (a == 0)
                attn_score_softmax<1><<<gScore, 256, SC_SMEM>>>(q, k, P,
                    DKK, DD, DD, (long)TT*DD, 64L, (long)TT*DD, 64L,
                    HH, 0.125f, dec, TT);
            else if (a == 1)
                attn_score_softmax<2><<<gScore, 256, SC_SMEM>>>(q, k, P,
                    DKK, DD, DD, (long)TT*DD, 64L, (long)TT*DD, 64L,
                    HH, 0.125f, enc, SS);
            else
                attn_score_softmax<0><<<gScore, 256, SC_SMEM>>>(q, k, P,
                    DKK, DD, DD, (long)TT*DD, 64L, (long)TT*DD, 64L,
                    HH, 0.125f, nullptr, 0);

            // ctx[b,t,h*64:] = P[b,h] @ V[b,:,h*64:]
            bgemm_tf32<false><<<gCtx, 256>>>(P, v, c,
                TT, DKK, TT, TT, DD, DD,
                (long)HH*TT*TT, (long)TT*TT, (long)TT*DD, 64L,
                (long)TT*DD, 64L, HH, nullptr);

            gemm_tf32<false,false><<<gProj, 256>>>(c, Wo, t, BT, DD, DD);
            add_ln<<<BT, 256>>>(t, x, x,
                ln_g + (long)(l*3 + a)*DD, ln_b + (long)(l*3 + a)*DD);
        }
        gemm_tf32<true ,false><<<gF1,   256>>>(x, W1 + (long)l*DD*DFF, h, BT, DFF, DD);
        gemm_tf32<false,false><<<gProj, 256>>>(h, W2 + (long)l*DFF*DD, t, BT, DD, DFF);
        add_ln<<<BT, 256>>>(t, x, x, nullptr, nullptr);
    }

    copyk<<<(BT*DD + 255)/256, 256>>>(x, out, (long)BT*DD);
}

// round 3
// speedup vs baseline: 3.8701x; 1.2171x over previous
#include <cuda_runtime.h>
#include <math.h>

// Problem dims
#define BB 16
#define TT 256
#define SS 256
#define NA 300
#define DD 512
#define HH 8
#define DKK 64
#define DFF 2048
#define LL 6

#define BT (BB*TT)                 // 4096
#define BHTT ((long)BB*HH*TT*TT)   // 8388608

// d_out layout (floats): x | self_attns | enc_attns | ast_attns
#define SELF_OFF 2097152L
#define ENC_OFF  (SELF_OFF + (long)LL*BHTT)
#define AST_OFF  (ENC_OFF  + (long)LL*BHTT)

// ------------- scratch -------------
__device__ float g_x[BT*DD];
__device__ float g_t[BT*DD];
__device__ float g_qkv[3*BT*DD];
__device__ float g_c[BT*DD];
__device__ float g_h[BT*DFF];
__device__ float g_multi[BB*SS*DD];
__device__ float g_ast1[BB*SS*DD];
__device__ float g_aste[BB*SS*DD];
__device__ float g_mm[BB*SS*SS];
__device__ float g_mmctx[BB*SS*DD];

// ------------- tf32 helpers -------------
__device__ __forceinline__ unsigned f2tf(float x) {
    unsigned u; asm("cvt.rna.tf32.f32 %0, %1;" : "=r"(u) : "f"(x)); return u;
}
__device__ __forceinline__ void mma_tf32(float* d,
    unsigned a0, unsigned a1, unsigned a2, unsigned a3,
    unsigned b0, unsigned b1)
{
    asm volatile(
        "mma.sync.aligned.m16n8k8.row.col.f32.tf32.tf32.f32 "
        "{%0,%1,%2,%3},{%4,%5,%6,%7},{%8,%9},{%0,%1,%2,%3};\n"
        : "+f"(d[0]), "+f"(d[1]), "+f"(d[2]), "+f"(d[3])
        : "r"(a0), "r"(a1), "r"(a2), "r"(a3), "r"(b0), "r"(b1));
}

// ---------------------------------------------------------------------
// gemm2: C[M,N] = A[M,K] @ B[K,N], row-major. 64x128x32 tiles, double-
// buffered smem, 256 threads (warps 2x4, warp tile 32x32). M%64==0,
// N%128==0, K%32==0. blockIdx.z selects (A, B + z*strB, C + z*strC);
// for plain GEMMs launch gridDim.z = 1 with A0==A1==A2.
// dynamic smem = 2*(64*36 + 32*136)*4 = 53248 bytes.
// ---------------------------------------------------------------------
template<bool RELU, bool ACC>
__global__ __launch_bounds__(256, 2) void gemm2(
    const float* __restrict__ A0, const float* __restrict__ A1,
    const float* __restrict__ A2,
    const float* __restrict__ B0, long strB,
    float* __restrict__ C0, long strC,
    int M, int N, int K)
{
    extern __shared__ unsigned smg[];
    unsigned* As = smg;            // 2 x (64*36)
    unsigned* Bs = smg + 2*2304;   // 2 x (32*136)

    const int tid = threadIdx.x, warp = tid >> 5, lane = tid & 31;
    const int g = lane >> 2, tg = lane & 3;
    const int wr = warp >> 2, wc = warp & 3;     // wr 0..1 (32 rows), wc 0..3 (32 cols)
    const int z = blockIdx.z;

    const float* A = (z == 0) ? A0 : (z == 1 ? A1 : A2);
    const float* At = A + (long)blockIdx.y * 64 * K;
    const float* Bt = B0 + (long)z * strB + blockIdx.x * 128;
    float* C = C0 + (long)z * strC;

    const int aR = tid >> 3, aC = (tid & 7) * 4;   // + p*32 rows
    const int bR = tid >> 5, bC = (tid & 31) * 4;  // + p*8 rows

    float4 ra[2], rb[4];
    #pragma unroll
    for (int p = 0; p < 2; p++)
        ra[p] = *reinterpret_cast<const float4*>(At + (long)(aR + p*32)*K + aC);
    #pragma unroll
    for (int p = 0; p < 4; p++)
        rb[p] = *reinterpret_cast<const float4*>(Bt + (long)(bR + p*8)*N + bC);

    auto sts = [&](int buf) {
        #pragma unroll
        for (int p = 0; p < 2; p++) {
            unsigned* d = &As[buf*2304 + (aR + p*32)*36 + aC];
            d[0]=f2tf(ra[p].x); d[1]=f2tf(ra[p].y); d[2]=f2tf(ra[p].z); d[3]=f2tf(ra[p].w);
        }
        #pragma unroll
        for (int p = 0; p < 4; p++) {
            unsigned* d = &Bs[buf*4352 + (bR + p*8)*136 + bC];
            d[0]=f2tf(rb[p].x); d[1]=f2tf(rb[p].y); d[2]=f2tf(rb[p].z); d[3]=f2tf(rb[p].w);
        }
    };
    sts(0);
    __syncthreads();

    float acc[8][4];
    #pragma unroll
    for (int i = 0; i < 8; i++) { acc[i][0]=0.f; acc[i][1]=0.f; acc[i][2]=0.f; acc[i][3]=0.f; }

    int cur = 0;
    for (int k0 = 0; k0 < K; k0 += 32) {
        const bool nxt = (k0 + 32) < K;
        if (nxt) {
            #pragma unroll
            for (int p = 0; p < 2; p++)
                ra[p] = *reinterpret_cast<const float4*>(At + (long)(aR + p*32)*K + k0 + 32 + aC);
            #pragma unroll
            for (int p = 0; p < 4; p++)
                rb[p] = *reinterpret_cast<const float4*>(Bt + (long)(k0 + 32 + bR + p*8)*N + bC);
        }
        const unsigned* Ab = &As[cur*2304];
        const unsigned* Bb = &Bs[cur*4352];
        #pragma unroll
        for (int ks = 0; ks < 4; ks++) {
            const int kk = ks * 8;
            unsigned a[2][4], b[4][2];
            #pragma unroll
            for (int mi = 0; mi < 2; mi++) {
                int mb = wr*32 + mi*16;
                a[mi][0] = Ab[(mb+g  )*36 + kk + tg];
                a[mi][1] = Ab[(mb+g+8)*36 + kk + tg];
                a[mi][2] = Ab[(mb+g  )*36 + kk + tg + 4];
                a[mi][3] = Ab[(mb+g+8)*36 + kk + tg + 4];
            }
            #pragma unroll
            for (int nj = 0; nj < 4; nj++) {
                int nb = wc*32 + nj*8;
                b[nj][0] = Bb[(kk+tg  )*136 + nb + g];
                b[nj][1] = Bb[(kk+tg+4)*136 + nb + g];
            }
            #pragma unroll
            for (int mi = 0; mi < 2; mi++)
                #pragma unroll
                for (int nj = 0; nj < 4; nj++)
                    mma_tf32(acc[mi*4+nj], a[mi][0],a[mi][1],a[mi][2],a[mi][3],
                             b[nj][0], b[nj][1]);
        }
        if (nxt) {
            sts(cur ^ 1);
            __syncthreads();
            cur ^= 1;
        }
    }

    #pragma unroll
    for (int mi = 0; mi < 2; mi++) {
        #pragma unroll
        for (int nj = 0; nj < 4; nj++) {
            float* d = acc[mi*4+nj];
            int r0 = blockIdx.y*64 + wr*32 + mi*16 + g;
            int col = blockIdx.x*128 + wc*32 + nj*8 + tg*2;
            float2 v0 = make_float2(d[0], d[1]);
            float2 v1 = make_float2(d[2], d[3]);
            float2* p0 = reinterpret_cast<float2*>(C + (long)r0*N + col);
            float2* p1 = reinterpret_cast<float2*>(C + (long)(r0+8)*N + col);
            if (ACC) { float2 o0 = *p0, o1 = *p1; v0.x+=o0.x; v0.y+=o0.y; v1.x+=o1.x; v1.y+=o1.y; }
            if (RELU) { v0.x=fmaxf(v0.x,0.f); v0.y=fmaxf(v0.y,0.f); v1.x=fmaxf(v1.x,0.f); v1.y=fmaxf(v1.y,0.f); }
            *p0 = v0; *p1 = v1;
        }
    }
}

// ---------------------------------------------------------------------
// attn_fused: S = scale * Q @ K^T (64 rows x 256 cols), mask, softmax,
// write P to gmem; if CTX, also ctx = P @ V (64 x 64) kept on-chip.
// 256 threads, warps 2x4. P row length fixed 256, per-z stride 65536.
// smem: Qs[64*68] | Ks[256*68] | Vs[256*68 (CTX)]; Ps[64*260] aliases Qs/Ks.
// MASK: 0 none, 1 pad|causal, 2 pad.
// ---------------------------------------------------------------------
template<int MASK, bool CTX>
__global__ __launch_bounds__(256) void attn_fused(
    const float* __restrict__ Q, const float* __restrict__ Km,
    const float* __restrict__ Vm, float* __restrict__ P,
    float* __restrict__ Cctx,
    int Kdim, int lda, int ldb,
    long strA, long offHA, long strB, long offHB,
    int Hh, float scale, const int* __restrict__ tok, int tokStride)
{
    extern __shared__ unsigned sma[];
    unsigned* Qs = sma;                      // 64*68
    unsigned* Ks = sma + 64*68;              // 256*68
    unsigned* Vs = sma + 64*68 + 256*68;     // 256*68 (CTX only)
    unsigned* Ps = sma;                      // 64*260, aliases Qs+Ks head
    __shared__ float red[64*4];

    const int tid = threadIdx.x, warp = tid >> 5, lane = tid & 31;
    const int g = lane >> 2, tg = lane & 3;
    const int wr = warp >> 2, wc = warp & 3;   // wr 0..1 (32 rows), wc 0..3 (64 cols)
    const int z = blockIdx.y;
    const int bb = z / Hh, hh = z - bb*Hh;
    const int rowTile = blockIdx.x;
    const int rowBase = rowTile * 64;

    const float* Qb = Q + (long)bb*strA + (long)hh*offHA + (long)rowBase*lda;
    const float* Kb = Km + (long)bb*strB + (long)hh*offHB;

    float acc[16][4];
    #pragma unroll
    for (int i = 0; i < 16; i++) { acc[i][0]=0.f; acc[i][1]=0.f; acc[i][2]=0.f; acc[i][3]=0.f; }

    for (int k0 = 0; k0 < Kdim; k0 += 64) {
        #pragma unroll
        for (int p = 0; p < 4; p++) {            // Q 64x64
            int idx = tid + p*256;
            int r = idx >> 4, c4 = idx & 15;
            float4 v = *reinterpret_cast<const float4*>(Qb + (long)r*lda + k0 + c4*4);
            unsigned* d = &Qs[r*68 + c4*4];
            d[0]=f2tf(v.x); d[1]=f2tf(v.y); d[2]=f2tf(v.z); d[3]=f2tf(v.w);
        }
        #pragma unroll
        for (int p = 0; p < 16; p++) {           // K 256x64
            int idx = tid + p*256;
            int r = idx >> 4, c4 = idx & 15;
            float4 v = *reinterpret_cast<const float4*>(Kb + (long)r*ldb + k0 + c4*4);
            unsigned* d = &Ks[r*68 + c4*4];
            d[0]=f2tf(v.x); d[1]=f2tf(v.y); d[2]=f2tf(v.z); d[3]=f2tf(v.w);
        }
        if (CTX && k0 == 0) {                    // V 256x64 (head slice)
            const float* Vb = Vm + (long)bb*strB + (long)hh*offHB;
            #pragma unroll
            for (int p = 0; p < 16; p++) {
                int idx = tid + p*256;
                int r = idx >> 4, c4 = idx & 15;
                float4 v = *reinterpret_cast<const float4*>(Vb + (long)r*ldb + c4*4);
                unsigned* d = &Vs[r*68 + c4*4];
                d[0]=f2tf(v.x); d[1]=f2tf(v.y); d[2]=f2tf(v.z); d[3]=f2tf(v.w);
            }
        }
        __syncthreads();
        #pragma unroll
        for (int ks = 0; ks < 8; ks++) {
            const int kk = ks * 8;
            unsigned a[2][4], b[8][2];
            #pragma unroll
            for (int mi = 0; mi < 2; mi++) {
                int mb = wr*32 + mi*16;
                a[mi][0] = Qs[(mb+g  )*68 + kk + tg];
                a[mi][1] = Qs[(mb+g+8)*68 + kk + tg];
                a[mi][2] = Qs[(mb+g  )*68 + kk + tg + 4];
                a[mi][3] = Qs[(mb+g+8)*68 + kk + tg + 4];
            }
            #pragma unroll
            for (int nj = 0; nj < 8; nj++) {
                int nb = wc*64 + nj*8;
                b[nj][0] = Ks[(nb+g)*68 + kk + tg];
                b[nj][1] = Ks[(nb+g)*68 + kk + tg + 4];
            }
            #pragma unroll
            for (int mi = 0; mi < 2; mi++)
                #pragma unroll
                for (int nj = 0; nj < 8; nj++)
                    mma_tf32(acc[mi*8+nj], a[mi][0],a[mi][1],a[mi][2],a[mi][3],
                             b[nj][0], b[nj][1]);
        }
        if (k0 + 64 < Kdim) __syncthreads();
    }

    // ---- scale + mask ----
    #pragma unroll
    for (int mi = 0; mi < 2; mi++) {
        #pragma unroll
        for (int nj = 0; nj < 8; nj++) {
            float* d = acc[mi*8+nj];
            int col = wc*64 + nj*8 + tg*2;
            int lr0 = wr*32 + mi*16 + g;
            #pragma unroll
            for (int c = 0; c < 4; c++) {
                int gcol = col + (c & 1);
                int grow = rowBase + lr0 + ((c >> 1) * 8);
                float v = d[c] * scale;
                if (MASK == 1) {
                    if (tok[bb*tokStride + gcol] == 0 || gcol > grow) v = -1e9f;
                } else if (MASK == 2) {
                    if (tok[bb*tokStride + gcol] == 0) v = -1e9f;
                }
                d[c] = v;
            }
        }
    }

    // ---- softmax over full 256-wide rows ----
    float rmax[4];
    #pragma unroll
    for (int mi = 0; mi < 2; mi++) {
        float m0 = -1e30f, m1 = -1e30f;
        #pragma unroll
        for (int nj = 0; nj < 8; nj++) {
            float* d = acc[mi*8+nj];
            m0 = fmaxf(m0, fmaxf(d[0], d[1]));
            m1 = fmaxf(m1, fmaxf(d[2], d[3]));
        }
        rmax[mi*2+0] = m0; rmax[mi*2+1] = m1;
    }
    #pragma unroll
    for (int i = 0; i < 4; i++) {
        rmax[i] = fmaxf(rmax[i], __shfl_xor_sync(0xffffffffu, rmax[i], 1));
        rmax[i] = fmaxf(rmax[i], __shfl_xor_sync(0xffffffffu, rmax[i], 2));
    }
    if (tg == 0) {
        #pragma unroll
        for (int mi = 0; mi < 2; mi++) {
            red[(wr*32 + mi*16 + g    )*4 + wc] = rmax[mi*2+0];
            red[(wr*32 + mi*16 + g + 8)*4 + wc] = rmax[mi*2+1];
        }
    }
    __syncthreads();
    float fmax4[4];
    #pragma unroll
    for (int mi = 0; mi < 2; mi++) {
        int r0 = wr*32 + mi*16 + g, r1 = r0 + 8;
        fmax4[mi*2+0] = fmaxf(fmaxf(red[r0*4+0], red[r0*4+1]), fmaxf(red[r0*4+2], red[r0*4+3]));
        fmax4[mi*2+1] = fmaxf(fmaxf(red[r1*4+0], red[r1*4+1]), fmaxf(red[r1*4+2], red[r1*4+3]));
    }
    __syncthreads();

    float rsum[4] = {0.f, 0.f, 0.f, 0.f};
    #pragma unroll
    for (int mi = 0; mi < 2; mi++) {
        #pragma unroll
        for (int nj = 0; nj < 8; nj++) {
            float* d = acc[mi*8+nj];
            d[0] = __expf(d[0] - fmax4[mi*2+0]);
            d[1] = __expf(d[1] - fmax4[mi*2+0]);
            d[2] = __expf(d[2] - fmax4[mi*2+1]);
            d[3] = __expf(d[3] - fmax4[mi*2+1]);
            rsum[mi*2+0] += d[0] + d[1];
            rsum[mi*2+1] += d[2] + d[3];
        }
    }
    #pragma unroll
    for (int i = 0; i < 4; i++) {
        rsum[i] += __shfl_xor_sync(0xffffffffu, rsum[i], 1);
        rsum[i] += __shfl_xor_sync(0xffffffffu, rsum[i], 2);
    }
    if (tg == 0) {
        #pragma unroll
        for (int mi = 0; mi < 2; mi++) {
            red[(wr*32 + mi*16 + g    )*4 + wc] = rsum[mi*2+0];
            red[(wr*32 + mi*16 + g + 8)*4 + wc] = rsum[mi*2+1];
        }
    }
    __syncthreads();
    float rinv[4];
    #pragma unroll
    for (int mi = 0; mi < 2; mi++) {
        int r0 = wr*32 + mi*16 + g, r1 = r0 + 8;
        rinv[mi*2+0] = 1.f / (red[r0*4+0] + red[r0*4+1] + red[r0*4+2] + red[r0*4+3]);
        rinv[mi*2+1] = 1.f / (red[r1*4+0] + red[r1*4+1] + red[r1*4+2] + red[r1*4+3]);
    }

    // ---- write P to gmem (+ Ps smem for ctx) ----
    float* Pb = P + (long)z * 65536L + (long)rowBase * 256;
    #pragma unroll
    for (int mi = 0; mi < 2; mi++) {
        #pragma unroll
        for (int nj = 0; nj < 8; nj++) {
            float* d = acc[mi*8+nj];
            int col = wc*64 + nj*8 + tg*2;
            int r0 = wr*32 + mi*16 + g;
            float p0 = d[0]*rinv[mi*2+0], p1 = d[1]*rinv[mi*2+0];
            float p2 = d[2]*rinv[mi*2+1], p3 = d[3]*rinv[mi*2+1];
            *reinterpret_cast<float2*>(Pb + (long)r0*256 + col) = make_float2(p0, p1);
            *reinterpret_cast<float2*>(Pb + (long)(r0+8)*256 + col) = make_float2(p2, p3);
            if (CTX) {
                Ps[r0*260 + col] = f2tf(p0); Ps[r0*260 + col + 1] = f2tf(p1);
                Ps[(r0+8)*260 + col] = f2tf(p2); Ps[(r0+8)*260 + col + 1] = f2tf(p3);
            }
        }
    }

    if (CTX) {
        __syncthreads();
        // ctx(64x64) = P(64x256) @ V(256x64); warp tile 32x16
        float acc2[4][4];
        #pragma unroll
        for (int i = 0; i < 4; i++) { acc2[i][0]=0.f; acc2[i][1]=0.f; acc2[i][2]=0.f; acc2[i][3]=0.f; }
        #pragma unroll 8
        for (int ks = 0; ks < 32; ks++) {
            const int kk = ks * 8;
            unsigned a[2][4], b[2][2];
            #pragma unroll
            for (int mi = 0; mi < 2; mi++) {
                int mb = wr*32 + mi*16;
                a[mi][0] = Ps[(mb+g  )*260 + kk + tg];
                a[mi][1] = Ps[(mb+g+8)*260 + kk + tg];
                a[mi][2] = Ps[(mb+g  )*260 + kk + tg + 4];
                a[mi][3] = Ps[(mb+g+8)*260 + kk + tg + 4];
            }
            #pragma unroll
            for (int nj = 0; nj < 2; nj++) {
                int nb = wc*16 + nj*8;
                b[nj][0] = Vs[(kk+tg  )*68 + nb + g];
                b[nj][1] = Vs[(kk+tg+4)*68 + nb + g];
            }
            #pragma unroll
            for (int mi = 0; mi < 2; mi++)
                #pragma unroll
                for (int nj = 0; nj < 2; nj++)
                    mma_tf32(acc2[mi*2+nj], a[mi][0],a[mi][1],a[mi][2],a[mi][3],
                             b[nj][0], b[nj][1]);
        }
        float* Cb = Cctx + (long)bb*TT*DD + hh*64;
        #pragma unroll
        for (int mi = 0; mi < 2; mi++) {
            #pragma unroll
            for (int nj = 0; nj < 2; nj++) {
                float* d = acc2[mi*2+nj];
                int r0 = rowBase + wr*32 + mi*16 + g;
                int col = wc*16 + nj*8 + tg*2;
                *reinterpret_cast<float2*>(Cb + (long)r0*DD + col) = make_float2(d[0], d[1]);
                *reinterpret_cast<float2*>(Cb + (long)(r0+8)*DD + col) = make_float2(d[2], d[3]);
            }
        }
    }
}

// ---------------------------------------------------------------------
// bgemm_tf32 (from R2): batched C[z] = A[z] @ B[z] (+ rowBias).
// Used for the conv1d (K=300) and mm_ctx (per-batch A and B).
// ---------------------------------------------------------------------
template<bool ROWBIAS>
__global__ __launch_bounds__(256) void bgemm_tf32(
    const float* __restrict__ A, const float* __restrict__ B,
    float* __restrict__ C, int M, int N, int K,
    int lda, int ldb, int ldc,
    long strA, long offHA, long strB, long offHB, long strC, long offHC,
    int Hh, const float* __restrict__ bias)
{
    __shared__ unsigned As[128*36];
    __shared__ unsigned Bs[32*72];
    const int tid = threadIdx.x, warp = tid >> 5, lane = tid & 31;
    const int g = lane >> 2, tg = lane & 3;
    const int wr = warp >> 1, wc = warp & 1;
    const int z = blockIdx.z;
    const int bb = z / Hh, hh = z - bb*Hh;

    const float* Ab = A + (long)bb*strA + (long)hh*offHA + (long)blockIdx.y*128*lda;
    const float* Bb = B + (long)bb*strB + (long)hh*offHB + (long)blockIdx.x*64;

    float acc[8][4];
    #pragma unroll
    for (int i = 0; i < 8; i++) { acc[i][0]=0.f; acc[i][1]=0.f; acc[i][2]=0.f; acc[i][3]=0.f; }

    for (int k0 = 0; k0 < K; k0 += 32) {
        if (k0 + 32 <= K && (lda & 3) == 0) {
            #pragma unroll
            for (int p = 0; p < 4; p++) {
                int idx = tid + p*256;
                int r = idx >> 3, c4 = idx & 7;
                float4 v = *reinterpret_cast<const float4*>(Ab + (long)r*lda + k0 + c4*4);
                unsigned* d = &As[r*36 + c4*4];
                d[0]=f2tf(v.x); d[1]=f2tf(v.y); d[2]=f2tf(v.z); d[3]=f2tf(v.w);
            }
        } else {
            #pragma unroll
            for (int p = 0; p < 16; p++) {
                int idx = tid + p*256;
                int r = idx >> 5, c = idx & 31;
                float v = (k0 + c < K) ? Ab[(long)r*lda + k0 + c] : 0.f;
                As[r*36 + c] = f2tf(v);
            }
        }
        #pragma unroll
        for (int p = 0; p < 2; p++) {
            int idx = tid + p*256;
            int r = idx >> 4, c4 = idx & 15;
            float4 v;
            if (k0 + r < K)
                v = *reinterpret_cast<const float4*>(Bb + (long)(k0 + r)*ldb + c4*4);
            else
                v = make_float4(0.f, 0.f, 0.f, 0.f);
            unsigned* d = &Bs[r*72 + c4*4];
            d[0]=f2tf(v.x); d[1]=f2tf(v.y); d[2]=f2tf(v.z); d[3]=f2tf(v.w);
        }
        __syncthreads();
        #pragma unroll
        for (int ks = 0; ks < 4; ks++) {
            const int kk = ks * 8;
            unsigned a[2][4], b[4][2];
            #pragma unroll
            for (int mi = 0; mi < 2; mi++) {
                int mb = wr*32 + mi*16;
                a[mi][0] = As[(mb+g  )*36 + kk + tg];
                a[mi][1] = As[(mb+g+8)*36 + kk + tg];
                a[mi][2] = As[(mb+g  )*36 + kk + tg + 4];
                a[mi][3] = As[(mb+g+8)*36 + kk + tg + 4];
            }
            #pragma unroll
            for (int nj = 0; nj < 4; nj++) {
                int nb = wc*32 + nj*8;
                b[nj][0] = Bs[(kk+tg  )*72 + nb + g];
                b[nj][1] = Bs[(kk+tg+4)*72 + nb + g];
            }
            #pragma unroll
            for (int mi = 0; mi < 2; mi++)
                #pragma unroll
                for (int nj = 0; nj < 4; nj++)
                    mma_tf32(acc[mi*4+nj], a[mi][0],a[mi][1],a[mi][2],a[mi][3],
                             b[nj][0], b[nj][1]);
        }
        __syncthreads();
    }

    float* Cb = C + (long)bb*strC + (long)hh*offHC;
    #pragma unroll
    for (int mi = 0; mi < 2; mi++) {
        #pragma unroll
        for (int nj = 0; nj < 4; nj++) {
            float* d = acc[mi*4+nj];
            int r0 = blockIdx.y*128 + wr*32 + mi*16 + g;
            int col = blockIdx.x*64 + wc*32 + nj*8 + tg*2;
            float b0 = ROWBIAS ? bias[r0] : 0.f;
            float b1 = ROWBIAS ? bias[r0+8] : 0.f;
            *reinterpret_cast<float2*>(Cb + (long)r0*ldc + col) =
                make_float2(d[0]+b0, d[1]+b0);
            *reinterpret_cast<float2*>(Cb + (long)(r0+8)*ldc + col) =
                make_float2(d[2]+b1, d[3]+b1);
        }
    }
}

// ---------------------------------------------------------------------
__global__ __launch_bounds__(256) void add_ln(
    const float* __restrict__ a, const float* __restrict__ b,
    float* __restrict__ out, const float* __restrict__ g,
    const float* __restrict__ beta)
{
    long off = (long)blockIdx.x * DD;
    int t = threadIdx.x;
    float v0 = a[off + t] + b[off + t];
    float v1 = a[off + t + 256] + b[off + t + 256];
    __shared__ float red[256];
    red[t] = v0 + v1; __syncthreads();
    for (int s = 128; s > 0; s >>= 1) { if (t < s) red[t] += red[t+s]; __syncthreads(); }
    float mu = red[0] * (1.f/DD); __syncthreads();
    float d0 = v0 - mu, d1 = v1 - mu;
    red[t] = d0*d0 + d1*d1; __syncthreads();
    for (int s = 128; s > 0; s >>= 1) { if (t < s) red[t] += red[t+s]; __syncthreads(); }
    float rstd = rsqrtf(red[0] * (1.f/DD) + 1e-5f);
    float g0 = g ? g[t] : 1.f,       g1 = g ? g[t+256] : 1.f;
    float b0 = beta ? beta[t] : 0.f, b1 = beta ? beta[t+256] : 0.f;
    out[off + t]       = d0 * rstd * g0 + b0;
    out[off + t + 256] = d1 * rstd * g1 + b1;
}

__global__ void embed_pe(const int* __restrict__ dec,
                         const float* __restrict__ emb,
                         float* __restrict__ x)
{
    long idx = (long)blockIdx.x * blockDim.x + threadIdx.x;
    if (idx >= (long)BT*DD) return;
    int d  = (int)(idx % DD);
    long bt = idx / DD;
    int t  = (int)(bt % TT);
    int tokidx = dec[bt];
    int d2 = d & ~1;
    float div = expf(-logf(10000.f) * (float)d2 / (float)DD);
    float ang = (float)t * div;
    float pe = (d & 1) ? cosf(ang) : sinf(ang);
    x[idx] = emb[(long)tokidx*DD + d] + pe;
}

__global__ void add3(const float* __restrict__ a, const float* __restrict__ bias,
                     const float* __restrict__ c, float* __restrict__ out, long n)
{
    long i = (long)blockIdx.x * blockDim.x + threadIdx.x;
    if (i >= n) return;
    out[i] = a[i] + bias[i % DD] + c[i];
}

__global__ void copyk(const float* __restrict__ src, float* __restrict__ dst, long n)
{
    long i = (long)blockIdx.x * blockDim.x + threadIdx.x;
    if (i < n) dst[i] = src[i];
}

// ---------------------------------------------------------------------
extern "C" void kernel_launch(void* const* d_in, const int* in_sizes, int n_in,
                              void* d_out, int out_size)
{
    const int*   dec     = (const int*)  d_in[0];
    const int*   enc     = (const int*)  d_in[1];
    const float* enc_out = (const float*)d_in[2];
    const float* ast_out = (const float*)d_in[3];
    const float* src_emb = (const float*)d_in[4];
    const float* ast_emb = (const float*)d_in[5];
    const float* emb     = (const float*)d_in[7];
    const float* attn_W  = (const float*)d_in[8];
    const float* ln_g    = (const float*)d_in[9];
    const float* ln_b    = (const float*)d_in[10];
    const float* W1      = (const float*)d_in[11];
    const float* W2      = (const float*)d_in[12];
    const float* conv_w  = (const float*)d_in[13];
    const float* conv_b  = (const float*)d_in[14];
    const float* mffnW   = (const float*)d_in[15];
    const float* mffnb   = (const float*)d_in[16];
    float* out = (float*)d_out;

    float *x,*t,*qkv,*c,*h,*multi,*ast1,*aste,*mm,*mmctx;
    cudaGetSymbolAddress((void**)&x,     g_x);
    cudaGetSymbolAddress((void**)&t,     g_t);
    cudaGetSymbolAddress((void**)&qkv,   g_qkv);
    cudaGetSymbolAddress((void**)&c,     g_c);
    cudaGetSymbolAddress((void**)&h,     g_h);
    cudaGetSymbolAddress((void**)&multi, g_multi);
    cudaGetSymbolAddress((void**)&ast1,  g_ast1);
    cudaGetSymbolAddress((void**)&aste,  g_aste);
    cudaGetSymbolAddress((void**)&mm,    g_mm);
    cudaGetSymbolAddress((void**)&mmctx, g_mmctx);

    const int GM_SMEM  = 2*(64*36 + 32*136)*4;                 // 53248
    const int AT_SMEM  = (64*68 + 2*256*68)*4;                 // 156672 (CTX)
    const int MM_SMEM  = (64*68 + 256*68)*4;                   // 87040  (no CTX)
    cudaFuncSetAttribute(gemm2<false,false>, cudaFuncAttributeMaxDynamicSharedMemorySize, GM_SMEM);
    cudaFuncSetAttribute(gemm2<false,true >, cudaFuncAttributeMaxDynamicSharedMemorySize, GM_SMEM);
    cudaFuncSetAttribute(gemm2<true ,false>, cudaFuncAttributeMaxDynamicSharedMemorySize, GM_SMEM);
    cudaFuncSetAttribute(attn_fused<0,false>, cudaFuncAttributeMaxDynamicSharedMemorySize, MM_SMEM);
    cudaFuncSetAttribute(attn_fused<0,true >, cudaFuncAttributeMaxDynamicSharedMemorySize, AT_SMEM);
    cudaFuncSetAttribute(attn_fused<1,true >, cudaFuncAttributeMaxDynamicSharedMemorySize, AT_SMEM);
    cudaFuncSetAttribute(attn_fused<2,true >, cudaFuncAttributeMaxDynamicSharedMemorySize, AT_SMEM);

    float* q = qkv;
    float* k = qkv + (long)BT*DD;
    float* v = qkv + 2L*BT*DD;

    // ---------------- multi_model preamble ----------------
    {
        dim3 grid(DD/64, SS/128, BB);
        bgemm_tf32<true><<<grid, 256>>>(conv_w, ast_out, ast1,
            SS, DD, NA, NA, DD, DD,
            0L, 0L, (long)NA*DD, 0L, (long)SS*DD, 0L, 1, conv_b);
        bgemm_tf32<true><<<grid, 256>>>(conv_w, ast_emb, aste,
            SS, DD, NA, NA, DD, DD,
            0L, 0L, (long)NA*DD, 0L, (long)SS*DD, 0L, 1, conv_b);
    }
    {
        dim3 gs(SS/64, BB);
        attn_fused<0,false><<<gs, 256, MM_SMEM>>>(ast1, enc_out, nullptr, mm, nullptr,
            DD, DD, DD, (long)SS*DD, 0L, (long)SS*DD, 0L,
            1, 0.125f, nullptr, 0);
        dim3 grid2(DD/64, SS/128, BB);
        bgemm_tf32<false><<<grid2, 256>>>(mm, enc_out, mmctx,
            SS, DD, SS, SS, DD, DD,
            (long)SS*SS, 0L, (long)SS*DD, 0L, (long)SS*DD, 0L, 1, nullptr);
    }
    {
        dim3 grid(DD/128, BT/64, 1);
        gemm2<false,false><<<grid, 256, GM_SMEM>>>(src_emb, src_emb, src_emb,
            mffnW, 0L, t, 0L, BT, DD, DD);
        gemm2<false,true ><<<grid, 256, GM_SMEM>>>(aste, aste, aste,
            mffnW + DD*DD, 0L, t, 0L, BT, DD, DD);
        long n = (long)BB*SS*DD;
        add3<<<(int)((n + 255)/256), 256>>>(t, mffnb, mmctx, multi, n);
    }
    embed_pe<<<(BT*DD + 255)/256, 256>>>(dec, emb, x);

    // ---------------- decoder layers ----------------
    dim3 gQKV(DD/128, BT/64, 3);
    dim3 gProj(DD/128, BT/64, 1);
    dim3 gF1(DFF/128, BT/64, 1);
    dim3 gScore(TT/64, BB*HH);

    for (int l = 0; l < LL; l++) {
        for (int a = 0; a < 3; a++) {
            const float* W = attn_W + ((long)(l*3 + a) * 4) * DD * DD;
            const float* Wo = W + 3L*DD*DD;
            const float* xk = (a == 0) ? x : (a == 1 ? enc_out : multi);

            // q/k/v in one launch: z=0 uses x@Wq, z=1 xk@Wk, z=2 xk@Wv
            gemm2<false,false><<<gQKV, 256, GM_SMEM>>>(x, xk, xk,
                W, (long)DD*DD, qkv, (long)BT*DD, BT, DD, DD);

            long attnBase = (a == 0 ? SELF_OFF : (a == 1 ? ENC_OFF : AST_OFF))
                            + (long)l * BHTT;
            float* P = out + attnBase;

            if (a == 0)
                attn_fused<1,true><<<gScore, 256, AT_SMEM>>>(q, k, v, P, c,
                    DKK, DD, DD, (long)TT*DD, 64L, (long)TT*DD, 64L,
                    HH, 0.125f, dec, TT);
            else if (a == 1)
                attn_fused<2,true><<<gScore, 256, AT_SMEM>>>(q, k, v, P, c,
                    DKK, DD, DD, (long)TT*DD, 64L, (long)TT*DD, 64L,
                    HH, 0.125f, enc, SS);
            else
                attn_fused<0,true><<<gScore, 256, AT_SMEM>>>(q, k, v, P, c,
                    DKK, DD, DD, (long)TT*DD, 64L, (long)TT*DD, 64L,
                    HH, 0.125f, nullptr, 0);

            gemm2<false,false><<<gProj, 256, GM_SMEM>>>(c, c, c,
                Wo, 0L, t, 0L, BT, DD, DD);
            add_ln<<<BT, 256>>>(t, x, x,
                ln_g + (long)(l*3 + a)*DD, ln_b + (long)(l*3 + a)*DD);
        }
        gemm2<true ,false><<<gF1, 256, GM_SMEM>>>(x, x, x,
            W1 + (long)l*DD*DFF, 0L, h, 0L, BT, DFF, DD);
        gemm2<false,false><<<gProj, 256, GM_SMEM>>>(h, h, h,
            W2 + (long)l*DFF*DD, 0L, t, 0L, BT, DD, DFF);
        add_ln<<<BT, 256>>>(t, x, x, nullptr, nullptr);
    }

    copyk<<<(BT*DD + 255)/256, 256>>>(x, out, (long)BT*DD);
}